// round 9
// baseline (speedup 1.0000x reference)
#include <cuda_runtime.h>
#include <cuda_bf16.h>
#include <cstdint>

// out[b, a*16+c, d, l] = sum_k s[b,(c-a)%16,l,k] * t[b,c,l,d-k]  (linear conv)
// Per (b,c,l): D[128d x 16m] = A[128x64] * B[16x64]^T,
//   A[d][k] = t_pad[d-k] (Toeplitz), B[m][k] = s[b,m,l,k].
// mma.sync.m16n8k16 bf16, 3-term truncation split (hi*hi + hi*lo + lo*hi).
// R8 restructure: block = (b, l-oct) with c-loop inside -- B (s-side) is
// c-independent, so s-load + B-build run ONCE per block (was 16x).

typedef unsigned int u32;

#define OFF_A    0
#define A_SIDE   3840          // 80 rows * 48B (hi/lo halves per l)
#define A_PERL   7680
#define OFF_TP   61440         // 8 * 96 floats
#define OFF_B    64512         // 16 rows * 144B * 2 sides * 8 l = 36864
#define B_SIDE   2304
#define B_PERL   4608
#define SMEM_TOTAL 101376
#define STG_MS   1156          // staging m-stride (floats)
#define SRS      516           // s_raw m-stride (floats), 16B-aligned rows

__device__ __forceinline__ u32 pack_bf2(float lo, float hi) {   // {lo16, hi16}
    u32 r;
    asm("cvt.rn.satfinite.bf16x2.f32 %0, %1, %2;" : "=r"(r) : "f"(hi), "f"(lo));
    return r;
}
__device__ __forceinline__ void mma_bf16(float* c, const u32* a, u32 b0, u32 b1) {
    asm("mma.sync.aligned.m16n8k16.row.col.f32.bf16.bf16.f32 "
        "{%0,%1,%2,%3}, {%4,%5,%6,%7}, {%8,%9}, {%0,%1,%2,%3};"
        : "+f"(c[0]), "+f"(c[1]), "+f"(c[2]), "+f"(c[3])
        : "r"(a[0]), "r"(a[1]), "r"(a[2]), "r"(a[3]), "r"(b0), "r"(b1));
}

__global__ __launch_bounds__(256, 2)
void conv_mma(const float* __restrict__ s_g,
              const float* __restrict__ t_g,
              float* __restrict__ out) {
    extern __shared__ char smem[];
    float* smf = (float*)smem;
    const int tid = threadIdx.x, wid = tid >> 5, lane = tid & 31;
    const int gid = lane >> 2, tig = lane & 3;
    const int lq = blockIdx.x, b = blockIdx.y;
    const int lbase = lq * 8;

    float* tp_f = (float*)(smem + OFF_TP);

    // ---- one-time: zero tp pads; stage s tile coalesced (overlays A region) ----
    for (int i = tid; i < 768; i += 256) tp_f[i] = 0.0f;
    float* s_raw = smf;
    {
        const float* sgb = s_g + ((size_t)b * 1024 + lbase) * 63;  // 16B-aligned
        for (int i = tid; i < 2016; i += 256) {                    // 16 m * 126 f4
            int m = i / 126, j = i - m * 126;
            float4 v = *(const float4*)(sgb + (size_t)m * 4032 + j * 4);
            *(float4*)(s_raw + m * SRS + j * 4) = v;
        }
    }
    __syncthreads();

    // ---- one-time: build B [l][side][16 m][64 k] bf16, 144B row stride ----
    {
        int h = tid & 1, mrow = tid >> 1, m = mrow & 15, l = mrow >> 4;
        const float* sp = s_raw + m * SRS + l * 63 + h * 32;
        u32 hw[16], lw[16];
        #pragma unroll
        for (int q = 0; q < 16; q++) {
            float x0 = sp[2 * q];                    // k = h*32+2q <= 62
            float x1 = 0.0f;
            if (h * 32 + 2 * q + 1 < 63) x1 = sp[2 * q + 1];
            u32 u0 = __float_as_uint(x0), u1 = __float_as_uint(x1);
            hw[q] = __byte_perm(u0, u1, 0x7632);     // {hi16(x0), hi16(x1)}
            float h0 = __uint_as_float(u0 & 0xFFFF0000u);
            float h1 = __uint_as_float(u1 & 0xFFFF0000u);
            lw[q] = pack_bf2(x0 - h0, x1 - h1);
        }
        char* bh = smem + OFF_B + l * B_PERL + m * 144 + h * 64;
        char* bl = bh + B_SIDE;
        #pragma unroll
        for (int cc = 0; cc < 4; cc++) {
            *(uint4*)(bh + cc * 16) =
                make_uint4(hw[cc*4], hw[cc*4+1], hw[cc*4+2], hw[cc*4+3]);
            *(uint4*)(bl + cc * 16) =
                make_uint4(lw[cc*4], lw[cc*4+1], lw[cc*4+2], lw[cc*4+3]);
        }
    }
    __syncthreads();   // B ready (persists); s_raw dead -> A/staging reuse region

    const int l_off = lane & 7, qq = lane >> 3;

    #pragma unroll 1
    for (int c = 0; c < 16; c++) {
        // ---- t load (coalesced) -> tp ----
        {
            const float* tg = t_g + (((size_t)b * 16 + c) * 64 + lbase) * 63;
            for (int i = tid; i < 504; i += 256) {
                int l = i / 63, k = i - l * 63;
                tp_f[l * 96 + 16 + k] = tg[i];
            }
        }
        __syncthreads();

        // ---- build banded A: Abar[l][side][rr][j] = t_pad[rr-j], rr in [0,80) ----
        for (int i = tid; i < 640; i += 256) {
            int l = i / 80, rr = i - (i / 80) * 80;
            const float* tpl = tp_f + l * 96 + 16 + rr;
            u32 hw[8], lw[8];
            #pragma unroll
            for (int q = 0; q < 8; q++) {
                float x0 = tpl[-(2 * q)], x1 = tpl[-(2 * q + 1)];
                u32 u0 = __float_as_uint(x0), u1 = __float_as_uint(x1);
                hw[q] = __byte_perm(u0, u1, 0x7632);
                float h0 = __uint_as_float(u0 & 0xFFFF0000u);
                float h1 = __uint_as_float(u1 & 0xFFFF0000u);
                lw[q] = pack_bf2(x0 - h0, x1 - h1);
            }
            char* ah = smem + OFF_A + l * A_PERL + rr * 48;
            char* al = ah + A_SIDE;
            *(uint4*)(ah)      = make_uint4(hw[0], hw[1], hw[2], hw[3]);
            *(uint4*)(ah + 16) = make_uint4(hw[4], hw[5], hw[6], hw[7]);
            *(uint4*)(al)      = make_uint4(lw[0], lw[1], lw[2], lw[3]);
            *(uint4*)(al + 16) = make_uint4(lw[4], lw[5], lw[6], lw[7]);
        }
        __syncthreads();

        // ---- mainloop: warp = l; two nt halves (register relief) ----
        float acc[2][8][4];
        const char* ab = smem + OFF_A + wid * A_PERL;
        const char* bb = smem + OFF_B + wid * B_PERL;
        #pragma unroll
        for (int nt = 0; nt < 2; nt++) {
            u32 bfr[4][2][2];   // [kt][side][b0/b1]
            #pragma unroll
            for (int kt = 0; kt < 4; kt++)
                #pragma unroll
                for (int sd = 0; sd < 2; sd++) {
                    const char* ad = bb + sd * B_SIDE + (8 * nt + gid) * 144
                                   + kt * 32 + tig * 4;
                    bfr[kt][sd][0] = *(const u32*)ad;
                    bfr[kt][sd][1] = *(const u32*)(ad + 16);
                }
            #pragma unroll
            for (int md = 0; md < 8; md++)
                #pragma unroll
                for (int e = 0; e < 4; e++) acc[nt][md][e] = 0.0f;

            #pragma unroll
            for (int sg = 0; sg < 5; sg++) {               // sigma = md - kt
                const char* ar = ab + sg * 768 + gid * 48 + tig * 4;
                u32 ah4[4] = { *(const u32*)ar,        *(const u32*)(ar + 384),
                               *(const u32*)(ar + 16), *(const u32*)(ar + 400) };
                const char* alp = ar + A_SIDE;
                u32 al4[4] = { *(const u32*)alp,        *(const u32*)(alp + 384),
                               *(const u32*)(alp + 16), *(const u32*)(alp + 400) };
                #pragma unroll
                for (int kt = 0; kt < 4; kt++) {
                    const int md = sg + kt;                // 0..7
                    mma_bf16(acc[nt][md], ah4, bfr[kt][0][0], bfr[kt][0][1]); // hi*hi
                    mma_bf16(acc[nt][md], ah4, bfr[kt][1][0], bfr[kt][1][1]); // hi*lo
                    mma_bf16(acc[nt][md], al4, bfr[kt][0][0], bfr[kt][0][1]); // lo*hi
                }
            }
        }
        __syncthreads();   // A dead; staging overlays A region

        // ---- two m-passes: stage (37KB over A region) + store ----
        #pragma unroll 1
        for (int p = 0; p < 2; p++) {
            #pragma unroll
            for (int md = 0; md < 8; md++) {
                int d0 = 16 * md + gid;
                float* st = smf + (2 * tig) * STG_MS + d0 * 9 + wid;
                st[0]            = acc[p][md][0];
                st[STG_MS]       = acc[p][md][1];
                st[72]           = acc[p][md][2];
                st[STG_MS + 72]  = acc[p][md][3];
            }
            __syncthreads();

            int m = 8 * p + wid;
            int a = (c - m) & 15;
            float* ob = out + ((size_t)(b * 256 + a * 16 + c) << 13)
                      + (size_t)(8 * qq) * 64 + lbase + l_off;
            const float* sm_m = smf + wid * STG_MS + 72 * qq + l_off;
            #pragma unroll
            for (int jj = 0; jj < 32; jj++) {
                int dlo = jj & 7, dhi = jj >> 3;
                ob[(size_t)(dlo + 32 * dhi) * 64] = sm_m[9 * dlo + 288 * dhi];
            }
            __syncthreads();
        }
    }
}

extern "C" void kernel_launch(void* const* d_in, const int* in_sizes, int n_in,
                              void* d_out, int out_size) {
    const float* s = (const float*)d_in[0];
    const float* t = (const float*)d_in[1];
    float* out = (float*)d_out;

    cudaFuncSetAttribute(conv_mma,
                         cudaFuncAttributeMaxDynamicSharedMemorySize, SMEM_TOTAL);

    dim3 grid(8, 32);   // (l-oct, b) = 256 blocks, c-loop inside
    conv_mma<<<grid, 256, SMEM_TOTAL>>>(s, t, out);
}

// round 10
// speedup vs baseline: 1.0603x; 1.0603x over previous
#include <cuda_runtime.h>
#include <cuda_bf16.h>
#include <cstdint>

// out[b, a*16+c, d, l] = sum_k s[b,(c-a)%16,l,k] * t[b,c,l,d-k]  (linear conv)
// Per (b,c,l): D[128d x 16m] = A[128x64] * B[16x64]^T,
//   A[d][k] = t_pad[d-k] (Toeplitz), B[m][k] = s[b,m,l,k].
// mma.sync.m16n8k16 bf16, 3-term truncation split (hi*hi + hi*lo + lo*hi).
// R10: block = (b, lq, c-quad), c-loop over 4 (B built once per block = 4x
// per (b,lq)); A-build reads t straight from global (coalesced per q,
// predicated pads) -- the tp smem phase and its barrier are gone.

typedef unsigned int u32;

#define OFF_A    0
#define A_SIDE   3840          // 80 rows * 48B (hi/lo halves per l)
#define A_PERL   7680
#define OFF_B    61440         // 16 rows * 144B * 2 sides * 8 l = 36864
#define B_SIDE   2304
#define B_PERL   4608
#define SMEM_TOTAL 98304
#define STG_MS   1156          // staging m-stride (floats)
#define SRS      516           // s_raw m-stride (floats), 16B-aligned rows

__device__ __forceinline__ u32 pack_bf2(float lo, float hi) {   // {lo16, hi16}
    u32 r;
    asm("cvt.rn.satfinite.bf16x2.f32 %0, %1, %2;" : "=r"(r) : "f"(hi), "f"(lo));
    return r;
}
__device__ __forceinline__ void mma_bf16(float* c, const u32* a, u32 b0, u32 b1) {
    asm("mma.sync.aligned.m16n8k16.row.col.f32.bf16.bf16.f32 "
        "{%0,%1,%2,%3}, {%4,%5,%6,%7}, {%8,%9}, {%0,%1,%2,%3};"
        : "+f"(c[0]), "+f"(c[1]), "+f"(c[2]), "+f"(c[3])
        : "r"(a[0]), "r"(a[1]), "r"(a[2]), "r"(a[3]), "r"(b0), "r"(b1));
}

__global__ __launch_bounds__(256, 2)
void conv_mma(const float* __restrict__ s_g,
              const float* __restrict__ t_g,
              float* __restrict__ out) {
    extern __shared__ char smem[];
    float* smf = (float*)smem;
    const int tid = threadIdx.x, wid = tid >> 5, lane = tid & 31;
    const int gid = lane >> 2, tig = lane & 3;
    const int lq = blockIdx.x, b = blockIdx.y, cg = blockIdx.z;
    const int lbase = lq * 8;

    // ---- once per block: stage s tile coalesced (overlays A region) ----
    float* s_raw = smf;
    {
        const float* sgb = s_g + ((size_t)b * 1024 + lbase) * 63;   // 16B-aligned
        for (int i = tid; i < 2016; i += 256) {                     // 16 m * 126 f4
            int m = i / 126, j = i - m * 126;
            float4 v = *(const float4*)(sgb + (size_t)m * 4032 + j * 4);
            *(float4*)(s_raw + m * SRS + j * 4) = v;
        }
    }
    __syncthreads();

    // ---- once per block: build B [l][side][16 m][64 k] bf16, 144B row stride ----
    {
        int h = tid & 1, mrow = tid >> 1, m = mrow & 15, l = mrow >> 4;
        const float* sp = s_raw + m * SRS + l * 63 + h * 32;
        u32 hw[16], lw[16];
        #pragma unroll
        for (int q = 0; q < 16; q++) {
            float x0 = sp[2 * q];                    // k = h*32+2q <= 62
            float x1 = 0.0f;
            if (h * 32 + 2 * q + 1 < 63) x1 = sp[2 * q + 1];
            u32 u0 = __float_as_uint(x0), u1 = __float_as_uint(x1);
            hw[q] = __byte_perm(u0, u1, 0x7632);     // {hi16(x0), hi16(x1)}
            float h0 = __uint_as_float(u0 & 0xFFFF0000u);
            float h1 = __uint_as_float(u1 & 0xFFFF0000u);
            lw[q] = pack_bf2(x0 - h0, x1 - h1);
        }
        char* bh = smem + OFF_B + l * B_PERL + m * 144 + h * 64;
        char* bl = bh + B_SIDE;
        #pragma unroll
        for (int cc = 0; cc < 4; cc++) {
            *(uint4*)(bh + cc * 16) =
                make_uint4(hw[cc*4], hw[cc*4+1], hw[cc*4+2], hw[cc*4+3]);
            *(uint4*)(bl + cc * 16) =
                make_uint4(lw[cc*4], lw[cc*4+1], lw[cc*4+2], lw[cc*4+3]);
        }
    }
    __syncthreads();   // B persists; A/staging region free

    const int l_off = lane & 7, qq = lane >> 3;

    #pragma unroll 1
    for (int ci = 0; ci < 4; ci++) {
        const int c = cg * 4 + ci;

        // ---- build banded A straight from global t (coalesced per q) ----
        // Abar[l][side][rr][j] = t_pad[rr - j], rr in [0,80), j in [0,16)
        for (int i = tid; i < 640; i += 256) {
            int l = i / 80, rr = i - (i / 80) * 80;
            const float* tg = t_g + (((size_t)b * 16 + c) * 64 + lbase + l) * 63;
            u32 hw[8], lw[8];
            #pragma unroll
            for (int q = 0; q < 8; q++) {
                int i0 = rr - 2 * q, i1 = i0 - 1;
                float x0 = ((unsigned)i0 < 63u) ? __ldg(tg + i0) : 0.0f;
                float x1 = ((unsigned)i1 < 63u) ? __ldg(tg + i1) : 0.0f;
                u32 u0 = __float_as_uint(x0), u1 = __float_as_uint(x1);
                hw[q] = __byte_perm(u0, u1, 0x7632);
                float h0 = __uint_as_float(u0 & 0xFFFF0000u);
                float h1 = __uint_as_float(u1 & 0xFFFF0000u);
                lw[q] = pack_bf2(x0 - h0, x1 - h1);
            }
            char* ah = smem + OFF_A + l * A_PERL + rr * 48;
            char* al = ah + A_SIDE;
            *(uint4*)(ah)      = make_uint4(hw[0], hw[1], hw[2], hw[3]);
            *(uint4*)(ah + 16) = make_uint4(hw[4], hw[5], hw[6], hw[7]);
            *(uint4*)(al)      = make_uint4(lw[0], lw[1], lw[2], lw[3]);
            *(uint4*)(al + 16) = make_uint4(lw[4], lw[5], lw[6], lw[7]);
        }
        __syncthreads();

        // ---- mainloop: warp = l; two nt halves ----
        float acc[2][8][4];
        const char* ab = smem + OFF_A + wid * A_PERL;
        const char* bb = smem + OFF_B + wid * B_PERL;
        #pragma unroll
        for (int nt = 0; nt < 2; nt++) {
            u32 bfr[4][2][2];   // [kt][side][b0/b1]
            #pragma unroll
            for (int kt = 0; kt < 4; kt++)
                #pragma unroll
                for (int sd = 0; sd < 2; sd++) {
                    const char* ad = bb + sd * B_SIDE + (8 * nt + gid) * 144
                                   + kt * 32 + tig * 4;
                    bfr[kt][sd][0] = *(const u32*)ad;
                    bfr[kt][sd][1] = *(const u32*)(ad + 16);
                }
            #pragma unroll
            for (int md = 0; md < 8; md++)
                #pragma unroll
                for (int e = 0; e < 4; e++) acc[nt][md][e] = 0.0f;

            #pragma unroll
            for (int sg = 0; sg < 5; sg++) {               // sigma = md - kt
                const char* ar = ab + sg * 768 + gid * 48 + tig * 4;
                u32 ah4[4] = { *(const u32*)ar,        *(const u32*)(ar + 384),
                               *(const u32*)(ar + 16), *(const u32*)(ar + 400) };
                const char* alp = ar + A_SIDE;
                u32 al4[4] = { *(const u32*)alp,        *(const u32*)(alp + 384),
                               *(const u32*)(alp + 16), *(const u32*)(alp + 400) };
                #pragma unroll
                for (int kt = 0; kt < 4; kt++) {
                    const int md = sg + kt;                // 0..7
                    mma_bf16(acc[nt][md], ah4, bfr[kt][0][0], bfr[kt][0][1]); // hi*hi
                    mma_bf16(acc[nt][md], ah4, bfr[kt][1][0], bfr[kt][1][1]); // hi*lo
                    mma_bf16(acc[nt][md], al4, bfr[kt][0][0], bfr[kt][0][1]); // lo*hi
                }
            }
        }
        __syncthreads();   // A dead; staging overlays A region

        // ---- two m-passes: stage (36KB over A region) + store ----
        #pragma unroll 1
        for (int p = 0; p < 2; p++) {
            #pragma unroll
            for (int md = 0; md < 8; md++) {
                int d0 = 16 * md + gid;
                float* st = smf + (2 * tig) * STG_MS + d0 * 9 + wid;
                st[0]            = acc[p][md][0];
                st[STG_MS]       = acc[p][md][1];
                st[72]           = acc[p][md][2];
                st[STG_MS + 72]  = acc[p][md][3];
            }
            __syncthreads();

            int m = 8 * p + wid;
            int a = (c - m) & 15;
            float* ob = out + ((size_t)(b * 256 + a * 16 + c) << 13)
                      + (size_t)(8 * qq) * 64 + lbase + l_off;
            const float* sm_m = smf + wid * STG_MS + 72 * qq + l_off;
            #pragma unroll
            for (int jj = 0; jj < 32; jj++) {
                int dlo = jj & 7, dhi = jj >> 3;
                ob[(size_t)(dlo + 32 * dhi) * 64] = sm_m[9 * dlo + 288 * dhi];
            }
            __syncthreads();
        }
    }
}

extern "C" void kernel_launch(void* const* d_in, const int* in_sizes, int n_in,
                              void* d_out, int out_size) {
    const float* s = (const float*)d_in[0];
    const float* t = (const float*)d_in[1];
    float* out = (float*)d_out;

    cudaFuncSetAttribute(conv_mma,
                         cudaFuncAttributeMaxDynamicSharedMemorySize, SMEM_TOTAL);

    dim3 grid(8, 32, 4);   // (l-oct, b, c-quad) = 1024 blocks, 4 c's each
    conv_mma<<<grid, 256, SMEM_TOTAL>>>(s, t, out);
}

// round 11
// speedup vs baseline: 1.3658x; 1.2881x over previous
#include <cuda_runtime.h>
#include <cuda_bf16.h>
#include <cstdint>

// out[b, a*16+c, d, l] = sum_k s[b,(c-a)%16,l,k] * t[b,c,l,d-k]  (linear conv)
// Per (b,c,l): D[128d x 16m] = A[128x64] * B[16x64]^T,
//   A[d][k] = t_pad[d-k] (Toeplitz), B[m][k] = s[b,m,l,k].
// mma.sync.m16n8k16 bf16, 3-term truncation split (hi*hi + hi*lo + lo*hi).
// R11: warp-autonomous builds (warp w owns l=w A/B slices), A-build(c+1)
// hoisted before the epilogue (overlaps its LDG latency with staging/stores),
// staging region separated from A (32B A rows). Barriers per c: 6 -> 4,
// loop-back edge barrier-free -> cross-warp phase overlap.

typedef unsigned int u32;

#define OFF_B    0
#define B_SIDE   2304          // 16 rows * 144B
#define B_PERL   4608          // x8 l = 36864
#define OFF_A    36864
#define A_SIDE   2560          // 80 rows * 32B
#define A_PERL   5120          // x8 l -> ends 77824
#define OFF_STG  77824
#define STG_MS   1156          // staging m-stride (floats)
#define SMEM_TOTAL 114816
#define SRS      516           // s_raw m-stride (floats), 16B-aligned rows

__device__ __forceinline__ u32 pack_bf2(float lo, float hi) {   // {lo16, hi16}
    u32 r;
    asm("cvt.rn.satfinite.bf16x2.f32 %0, %1, %2;" : "=r"(r) : "f"(hi), "f"(lo));
    return r;
}
__device__ __forceinline__ void mma_bf16(float* c, const u32* a, u32 b0, u32 b1) {
    asm("mma.sync.aligned.m16n8k16.row.col.f32.bf16.bf16.f32 "
        "{%0,%1,%2,%3}, {%4,%5,%6,%7}, {%8,%9}, {%0,%1,%2,%3};"
        : "+f"(c[0]), "+f"(c[1]), "+f"(c[2]), "+f"(c[3])
        : "r"(a[0]), "r"(a[1]), "r"(a[2]), "r"(a[3]), "r"(b0), "r"(b1));
}

// warp-local banded-A build for l = w: Abar[rr][j] = t_pad[rr-j], rr in [0,80)
__device__ __forceinline__ void build_A(char* smem, const float* __restrict__ tg,
                                        int w, int lane) {
    #pragma unroll
    for (int j = 0; j < 3; j++) {
        int rr = lane + 32 * j;
        if (rr < 80) {
            u32 hw[8], lw[8];
            #pragma unroll
            for (int q = 0; q < 8; q++) {
                int i0 = rr - 2 * q, i1 = i0 - 1;
                float x0 = ((unsigned)i0 < 63u) ? __ldg(tg + i0) : 0.0f;
                float x1 = ((unsigned)i1 < 63u) ? __ldg(tg + i1) : 0.0f;
                u32 u0 = __float_as_uint(x0), u1 = __float_as_uint(x1);
                hw[q] = __byte_perm(u0, u1, 0x7632);        // {hi16(x0), hi16(x1)}
                float h0 = __uint_as_float(u0 & 0xFFFF0000u);
                float h1 = __uint_as_float(u1 & 0xFFFF0000u);
                lw[q] = pack_bf2(x0 - h0, x1 - h1);
            }
            char* ah = smem + OFF_A + w * A_PERL + rr * 32;
            char* al = ah + A_SIDE;
            *(uint4*)(ah)      = make_uint4(hw[0], hw[1], hw[2], hw[3]);
            *(uint4*)(ah + 16) = make_uint4(hw[4], hw[5], hw[6], hw[7]);
            *(uint4*)(al)      = make_uint4(lw[0], lw[1], lw[2], lw[3]);
            *(uint4*)(al + 16) = make_uint4(lw[4], lw[5], lw[6], lw[7]);
        }
    }
}

__global__ __launch_bounds__(256, 2)
void conv_mma(const float* __restrict__ s_g,
              const float* __restrict__ t_g,
              float* __restrict__ out) {
    extern __shared__ char smem[];
    float* stgf = (float*)(smem + OFF_STG);
    const int tid = threadIdx.x, wid = tid >> 5, lane = tid & 31;
    const int gid = lane >> 2, tig = lane & 3;
    const int lq = blockIdx.x, b = blockIdx.y, cg = blockIdx.z;
    const int lbase = lq * 8;
    const float* tbase = t_g + (((size_t)b * 16 + cg * 4) * 64 + lbase + wid) * 63;

    // ---- prologue: stage s tile coalesced into staging region ----
    float* s_raw = stgf;
    {
        const float* sgb = s_g + ((size_t)b * 1024 + lbase) * 63;   // 16B-aligned
        for (int i = tid; i < 2016; i += 256) {                     // 16 m * 126 f4
            int m = i / 126, j = i - m * 126;
            float4 v = *(const float4*)(sgb + (size_t)m * 4032 + j * 4);
            *(float4*)(s_raw + m * SRS + j * 4) = v;
        }
    }
    __syncthreads();

    // ---- warp-local B build: warp w -> l = w; lane = (m, h) ----
    {
        int m = lane >> 1, h = lane & 1;
        const float* sp = s_raw + m * SRS + wid * 63 + h * 32;
        u32 hw[16], lw[16];
        #pragma unroll
        for (int q = 0; q < 16; q++) {
            float x0 = sp[2 * q];                    // k = h*32+2q <= 62
            float x1 = 0.0f;
            if (h * 32 + 2 * q + 1 < 63) x1 = sp[2 * q + 1];
            u32 u0 = __float_as_uint(x0), u1 = __float_as_uint(x1);
            hw[q] = __byte_perm(u0, u1, 0x7632);
            float h0 = __uint_as_float(u0 & 0xFFFF0000u);
            float h1 = __uint_as_float(u1 & 0xFFFF0000u);
            lw[q] = pack_bf2(x0 - h0, x1 - h1);
        }
        char* bh = smem + OFF_B + wid * B_PERL + m * 144 + h * 64;
        char* bl = bh + B_SIDE;
        #pragma unroll
        for (int cc = 0; cc < 4; cc++) {
            *(uint4*)(bh + cc * 16) =
                make_uint4(hw[cc*4], hw[cc*4+1], hw[cc*4+2], hw[cc*4+3]);
            *(uint4*)(bl + cc * 16) =
                make_uint4(lw[cc*4], lw[cc*4+1], lw[cc*4+2], lw[cc*4+3]);
        }
    }
    // ---- warp-local A build for first c ----
    build_A(smem, tbase, wid, lane);
    __syncthreads();   // s_raw consumed -> staging region free; B/A(c0) ready

    const int l_off = lane & 7, qq = lane >> 3;
    const char* ab = smem + OFF_A + wid * A_PERL;
    const char* bb = smem + OFF_B + wid * B_PERL;

    #pragma unroll 1
    for (int ci = 0; ci < 4; ci++) {
        const int c = cg * 4 + ci;

        // ---- mainloop: warp = l; two nt halves ----
        float acc[2][8][4];
        #pragma unroll
        for (int nt = 0; nt < 2; nt++) {
            u32 bfr[4][2][2];   // [kt][side][b0/b1]
            #pragma unroll
            for (int kt = 0; kt < 4; kt++)
                #pragma unroll
                for (int sd = 0; sd < 2; sd++) {
                    const char* ad = bb + sd * B_SIDE + (8 * nt + gid) * 144
                                   + kt * 32 + tig * 4;
                    bfr[kt][sd][0] = *(const u32*)ad;
                    bfr[kt][sd][1] = *(const u32*)(ad + 16);
                }
            #pragma unroll
            for (int md = 0; md < 8; md++)
                #pragma unroll
                for (int e = 0; e < 4; e++) acc[nt][md][e] = 0.0f;

            #pragma unroll
            for (int sg = 0; sg < 5; sg++) {               // sigma = md - kt
                const char* ar = ab + sg * 512 + gid * 32 + tig * 4;
                u32 ah4[4] = { *(const u32*)ar,        *(const u32*)(ar + 256),
                               *(const u32*)(ar + 16), *(const u32*)(ar + 272) };
                const char* alp = ar + A_SIDE;
                u32 al4[4] = { *(const u32*)alp,        *(const u32*)(alp + 256),
                               *(const u32*)(alp + 16), *(const u32*)(alp + 272) };
                #pragma unroll
                for (int kt = 0; kt < 4; kt++) {
                    const int md = sg + kt;                // 0..7
                    mma_bf16(acc[nt][md], ah4, bfr[kt][0][0], bfr[kt][0][1]); // hi*hi
                    mma_bf16(acc[nt][md], ah4, bfr[kt][1][0], bfr[kt][1][1]); // hi*lo
                    mma_bf16(acc[nt][md], al4, bfr[kt][0][0], bfr[kt][0][1]); // lo*hi
                }
            }
        }

        // ---- hoisted A build for c+1 (own slice; overlaps epilogue) ----
        if (ci < 3)
            build_A(smem, tbase + (size_t)(ci + 1) * 64 * 63, wid, lane);

        __syncthreads();   // prev store p1 readers done -> staging writable

        // ---- two m-passes: stage + store ----
        #pragma unroll 1
        for (int p = 0; p < 2; p++) {
            #pragma unroll
            for (int md = 0; md < 8; md++) {
                int d0 = 16 * md + gid;
                float* st = stgf + (2 * tig) * STG_MS + d0 * 9 + wid;
                st[0]            = acc[p][md][0];
                st[STG_MS]       = acc[p][md][1];
                st[72]           = acc[p][md][2];
                st[STG_MS + 72]  = acc[p][md][3];
            }
            __syncthreads();

            int m = 8 * p + wid;
            int a = (c - m) & 15;
            float* ob = out + ((size_t)(b * 256 + a * 16 + c) << 13)
                      + (size_t)(8 * qq) * 64 + lbase + l_off;
            const float* sm_m = stgf + wid * STG_MS + 72 * qq + l_off;
            #pragma unroll
            for (int jj = 0; jj < 32; jj++) {
                int dlo = jj & 7, dhi = jj >> 3;
                ob[(size_t)(dlo + 32 * dhi) * 64] = sm_m[9 * dlo + 288 * dhi];
            }
            if (p == 0) __syncthreads();   // store p0 reads done before stage p1
        }
        // no trailing barrier: next mainloop touches only warp-private A/B;
        // next iteration's pre-stage barrier protects the staging region.
    }
}

extern "C" void kernel_launch(void* const* d_in, const int* in_sizes, int n_in,
                              void* d_out, int out_size) {
    const float* s = (const float*)d_in[0];
    const float* t = (const float*)d_in[1];
    float* out = (float*)d_out;

    cudaFuncSetAttribute(conv_mma,
                         cudaFuncAttributeMaxDynamicSharedMemorySize, SMEM_TOTAL);

    dim3 grid(8, 32, 4);   // (l-oct, b, c-quad) = 1024 blocks, 4 c's each
    conv_mma<<<grid, 256, SMEM_TOTAL>>>(s, t, out);
}

// round 12
// speedup vs baseline: 1.3733x; 1.0055x over previous
#include <cuda_runtime.h>
#include <cuda_bf16.h>
#include <cstdint>

// out[b, a*16+c, d, l] = sum_k s[b,(c-a)%16,l,k] * t[b,c,l,d-k]  (linear conv)
// Per (b,c,l): D[128d x 16m] = A[128x64] * B[16x64]^T,
//   A[d][k] = t_pad[d-k] (Toeplitz), B[m][k] = s[b,m,l,k].
// mma.sync.m16n8k16 bf16, 3-term truncation split (hi*hi + hi*lo + lo*hi).
// R12: nt fused with epilogue pass p (mma nt0 -> stage/store p0 -> mma nt1 ->
// stage/store p1): tensor bursts fill the L1 store-drain windows; acc regs
// halve. A-build(c+1) still hoisted (warp-private). 4 barriers/c.

typedef unsigned int u32;

#define OFF_B    0
#define B_SIDE   2304          // 16 rows * 144B
#define B_PERL   4608          // x8 l = 36864
#define OFF_A    36864
#define A_SIDE   2560          // 80 rows * 32B
#define A_PERL   5120          // x8 l -> ends 77824
#define OFF_STG  77824
#define STG_MS   1156          // staging m-stride (floats)
#define SMEM_TOTAL 114816
#define SRS      516           // s_raw m-stride (floats), 16B-aligned rows

__device__ __forceinline__ u32 pack_bf2(float lo, float hi) {   // {lo16, hi16}
    u32 r;
    asm("cvt.rn.satfinite.bf16x2.f32 %0, %1, %2;" : "=r"(r) : "f"(hi), "f"(lo));
    return r;
}
__device__ __forceinline__ void mma_bf16(float* c, const u32* a, u32 b0, u32 b1) {
    asm("mma.sync.aligned.m16n8k16.row.col.f32.bf16.bf16.f32 "
        "{%0,%1,%2,%3}, {%4,%5,%6,%7}, {%8,%9}, {%0,%1,%2,%3};"
        : "+f"(c[0]), "+f"(c[1]), "+f"(c[2]), "+f"(c[3])
        : "r"(a[0]), "r"(a[1]), "r"(a[2]), "r"(a[3]), "r"(b0), "r"(b1));
}

// warp-local banded-A build for l = w: Abar[rr][j] = t_pad[rr-j], rr in [0,80)
__device__ __forceinline__ void build_A(char* smem, const float* __restrict__ tg,
                                        int w, int lane) {
    #pragma unroll
    for (int j = 0; j < 3; j++) {
        int rr = lane + 32 * j;
        if (rr < 80) {
            u32 hw[8], lw[8];
            #pragma unroll
            for (int q = 0; q < 8; q++) {
                int i0 = rr - 2 * q, i1 = i0 - 1;
                float x0 = ((unsigned)i0 < 63u) ? __ldg(tg + i0) : 0.0f;
                float x1 = ((unsigned)i1 < 63u) ? __ldg(tg + i1) : 0.0f;
                u32 u0 = __float_as_uint(x0), u1 = __float_as_uint(x1);
                hw[q] = __byte_perm(u0, u1, 0x7632);        // {hi16(x0), hi16(x1)}
                float h0 = __uint_as_float(u0 & 0xFFFF0000u);
                float h1 = __uint_as_float(u1 & 0xFFFF0000u);
                lw[q] = pack_bf2(x0 - h0, x1 - h1);
            }
            char* ah = smem + OFF_A + w * A_PERL + rr * 32;
            char* al = ah + A_SIDE;
            *(uint4*)(ah)      = make_uint4(hw[0], hw[1], hw[2], hw[3]);
            *(uint4*)(ah + 16) = make_uint4(hw[4], hw[5], hw[6], hw[7]);
            *(uint4*)(al)      = make_uint4(lw[0], lw[1], lw[2], lw[3]);
            *(uint4*)(al + 16) = make_uint4(lw[4], lw[5], lw[6], lw[7]);
        }
    }
}

__global__ __launch_bounds__(256, 2)
void conv_mma(const float* __restrict__ s_g,
              const float* __restrict__ t_g,
              float* __restrict__ out) {
    extern __shared__ char smem[];
    float* stgf = (float*)(smem + OFF_STG);
    const int tid = threadIdx.x, wid = tid >> 5, lane = tid & 31;
    const int gid = lane >> 2, tig = lane & 3;
    const int lq = blockIdx.x, b = blockIdx.y, cg = blockIdx.z;
    const int lbase = lq * 8;
    const float* tbase = t_g + (((size_t)b * 16 + cg * 4) * 64 + lbase + wid) * 63;

    // ---- prologue: stage s tile coalesced into staging region ----
    float* s_raw = stgf;
    {
        const float* sgb = s_g + ((size_t)b * 1024 + lbase) * 63;   // 16B-aligned
        for (int i = tid; i < 2016; i += 256) {                     // 16 m * 126 f4
            int m = i / 126, j = i - m * 126;
            float4 v = *(const float4*)(sgb + (size_t)m * 4032 + j * 4);
            *(float4*)(s_raw + m * SRS + j * 4) = v;
        }
    }
    __syncthreads();

    // ---- warp-local B build: warp w -> l = w; lane = (m, h) ----
    {
        int m = lane >> 1, h = lane & 1;
        const float* sp = s_raw + m * SRS + wid * 63 + h * 32;
        u32 hw[16], lw[16];
        #pragma unroll
        for (int q = 0; q < 16; q++) {
            float x0 = sp[2 * q];                    // k = h*32+2q <= 62
            float x1 = 0.0f;
            if (h * 32 + 2 * q + 1 < 63) x1 = sp[2 * q + 1];
            u32 u0 = __float_as_uint(x0), u1 = __float_as_uint(x1);
            hw[q] = __byte_perm(u0, u1, 0x7632);
            float h0 = __uint_as_float(u0 & 0xFFFF0000u);
            float h1 = __uint_as_float(u1 & 0xFFFF0000u);
            lw[q] = pack_bf2(x0 - h0, x1 - h1);
        }
        char* bh = smem + OFF_B + wid * B_PERL + m * 144 + h * 64;
        char* bl = bh + B_SIDE;
        #pragma unroll
        for (int cc = 0; cc < 4; cc++) {
            *(uint4*)(bh + cc * 16) =
                make_uint4(hw[cc*4], hw[cc*4+1], hw[cc*4+2], hw[cc*4+3]);
            *(uint4*)(bl + cc * 16) =
                make_uint4(lw[cc*4], lw[cc*4+1], lw[cc*4+2], lw[cc*4+3]);
        }
    }
    // ---- warp-local A build for first c ----
    build_A(smem, tbase, wid, lane);
    __syncthreads();   // s_raw consumed -> staging free; B/A(c0) ready

    const int l_off = lane & 7, qq = lane >> 3;
    const char* ab = smem + OFF_A + wid * A_PERL;
    const char* bb = smem + OFF_B + wid * B_PERL;

    #pragma unroll 1
    for (int ci = 0; ci < 4; ci++) {
        const int c = cg * 4 + ci;

        #pragma unroll 1
        for (int p = 0; p < 2; p++) {          // p doubles as nt
            // ---- mainloop half: n-tile nt = p for this warp's l ----
            float acc[8][4];
            u32 bfr[4][2][2];   // [kt][side][b0/b1]
            #pragma unroll
            for (int kt = 0; kt < 4; kt++)
                #pragma unroll
                for (int sd = 0; sd < 2; sd++) {
                    const char* ad = bb + sd * B_SIDE + (8 * p + gid) * 144
                                   + kt * 32 + tig * 4;
                    bfr[kt][sd][0] = *(const u32*)ad;
                    bfr[kt][sd][1] = *(const u32*)(ad + 16);
                }
            #pragma unroll
            for (int md = 0; md < 8; md++)
                #pragma unroll
                for (int e = 0; e < 4; e++) acc[md][e] = 0.0f;

            #pragma unroll
            for (int sg = 0; sg < 5; sg++) {               // sigma = md - kt
                const char* ar = ab + sg * 512 + gid * 32 + tig * 4;
                u32 ah4[4] = { *(const u32*)ar,        *(const u32*)(ar + 256),
                               *(const u32*)(ar + 16), *(const u32*)(ar + 272) };
                const char* alp = ar + A_SIDE;
                u32 al4[4] = { *(const u32*)alp,        *(const u32*)(alp + 256),
                               *(const u32*)(alp + 16), *(const u32*)(alp + 272) };
                #pragma unroll
                for (int kt = 0; kt < 4; kt++) {
                    const int md = sg + kt;                // 0..7
                    mma_bf16(acc[md], ah4, bfr[kt][0][0], bfr[kt][0][1]); // hi*hi
                    mma_bf16(acc[md], ah4, bfr[kt][1][0], bfr[kt][1][1]); // hi*lo
                    mma_bf16(acc[md], al4, bfr[kt][0][0], bfr[kt][0][1]); // lo*hi
                }
            }

            // ---- hoisted A build for c+1 (own slice; overlaps epilogue) ----
            if (p == 1 && ci < 3)
                build_A(smem, tbase + (size_t)(ci + 1) * 64 * 63, wid, lane);

            __syncthreads();   // staging writable (prev store readers done)

            // ---- stage this half's 8 m ----
            #pragma unroll
            for (int md = 0; md < 8; md++) {
                int d0 = 16 * md + gid;
                float* st = stgf + (2 * tig) * STG_MS + d0 * 9 + wid;
                st[0]            = acc[md][0];
                st[STG_MS]       = acc[md][1];
                st[72]           = acc[md][2];
                st[STG_MS + 72]  = acc[md][3];
            }
            __syncthreads();

            // ---- store (streamed) ----
            int m = 8 * p + wid;
            int a = (c - m) & 15;
            float* ob = out + ((size_t)(b * 256 + a * 16 + c) << 13)
                      + (size_t)(8 * qq) * 64 + lbase + l_off;
            const float* sm_m = stgf + wid * STG_MS + 72 * qq + l_off;
            #pragma unroll
            for (int jj = 0; jj < 32; jj++) {
                int dlo = jj & 7, dhi = jj >> 3;
                __stcs(ob + (size_t)(dlo + 32 * dhi) * 64,
                       sm_m[9 * dlo + 288 * dhi]);
            }
            // no trailing barrier: next mma half touches only warp-private
            // A/B; the next pre-stage barrier protects the staging region.
        }
    }
}

extern "C" void kernel_launch(void* const* d_in, const int* in_sizes, int n_in,
                              void* d_out, int out_size) {
    const float* s = (const float*)d_in[0];
    const float* t = (const float*)d_in[1];
    float* out = (float*)d_out;

    cudaFuncSetAttribute(conv_mma,
                         cudaFuncAttributeMaxDynamicSharedMemorySize, SMEM_TOTAL);

    dim3 grid(8, 32, 4);   // (l-oct, b, c-quad) = 1024 blocks, 4 c's each
    conv_mma<<<grid, 256, SMEM_TOTAL>>>(s, t, out);
}

// round 13
// speedup vs baseline: 1.3871x; 1.0100x over previous
#include <cuda_runtime.h>
#include <cuda_bf16.h>
#include <cstdint>

// out[b, a*16+c, d, l] = sum_k s[b,(c-a)%16,l,k] * t[b,c,l,d-k]  (linear conv)
// Per (b,c,l): D[128d x 16m] = A[128x64] * B[16x64]^T,
//   A[d][k] = t_pad[d-k] (Toeplitz), B[m][k] = s[b,m,l,k].
// mma.sync.m16n8k16 bf16, 3-term truncation split (hi*hi + hi*lo + lo*hi).
// R13: (1) A rows half-swizzled (swap 16B halves when rr&4) -> A-fragment
// LDS conflict-free (was 2-way, the largest L1 item); (2) grid z=8 (2 c per
// block) -> 6.92 waves, tail waste ~10% -> ~1%.

typedef unsigned int u32;

#define OFF_B    0
#define B_SIDE   2304          // 16 rows * 144B
#define B_PERL   4608          // x8 l = 36864
#define OFF_A    36864
#define A_SIDE   2560          // 80 rows * 32B
#define A_PERL   5120          // x8 l -> ends 77824
#define OFF_STG  77824
#define STG_MS   1156          // staging m-stride (floats)
#define SMEM_TOTAL 114816
#define SRS      516           // s_raw m-stride (floats), 16B-aligned rows

__device__ __forceinline__ u32 pack_bf2(float lo, float hi) {   // {lo16, hi16}
    u32 r;
    asm("cvt.rn.satfinite.bf16x2.f32 %0, %1, %2;" : "=r"(r) : "f"(hi), "f"(lo));
    return r;
}
__device__ __forceinline__ void mma_bf16(float* c, const u32* a, u32 b0, u32 b1) {
    asm("mma.sync.aligned.m16n8k16.row.col.f32.bf16.bf16.f32 "
        "{%0,%1,%2,%3}, {%4,%5,%6,%7}, {%8,%9}, {%0,%1,%2,%3};"
        : "+f"(c[0]), "+f"(c[1]), "+f"(c[2]), "+f"(c[3])
        : "r"(a[0]), "r"(a[1]), "r"(a[2]), "r"(a[3]), "r"(b0), "r"(b1));
}

// warp-local banded-A build for l = w: Abar[rr][j] = t_pad[rr-j], rr in [0,80)
// Half-swizzle: the two 16B halves of each 32B row are swapped when rr&4,
// making fragment-load bank starts {0,8,16,24,4,12,20,28} -> conflict-free.
__device__ __forceinline__ void build_A(char* smem, const float* __restrict__ tg,
                                        int w, int lane) {
    #pragma unroll
    for (int j = 0; j < 3; j++) {
        int rr = lane + 32 * j;
        if (rr < 80) {
            u32 hw[8], lw[8];
            #pragma unroll
            for (int q = 0; q < 8; q++) {
                int i0 = rr - 2 * q, i1 = i0 - 1;
                float x0 = ((unsigned)i0 < 63u) ? __ldg(tg + i0) : 0.0f;
                float x1 = ((unsigned)i1 < 63u) ? __ldg(tg + i1) : 0.0f;
                u32 u0 = __float_as_uint(x0), u1 = __float_as_uint(x1);
                hw[q] = __byte_perm(u0, u1, 0x7632);        // {hi16(x0), hi16(x1)}
                float h0 = __uint_as_float(u0 & 0xFFFF0000u);
                float h1 = __uint_as_float(u1 & 0xFFFF0000u);
                lw[q] = pack_bf2(x0 - h0, x1 - h1);
            }
            const int sk = (rr & 4) << 2;                   // 16 if rr&4 else 0
            char* ah = smem + OFF_A + w * A_PERL + rr * 32;
            char* al = ah + A_SIDE;
            *(uint4*)(ah + sk)        = make_uint4(hw[0], hw[1], hw[2], hw[3]);
            *(uint4*)(ah + (16 - sk)) = make_uint4(hw[4], hw[5], hw[6], hw[7]);
            *(uint4*)(al + sk)        = make_uint4(lw[0], lw[1], lw[2], lw[3]);
            *(uint4*)(al + (16 - sk)) = make_uint4(lw[4], lw[5], lw[6], lw[7]);
        }
    }
}

__global__ __launch_bounds__(256, 2)
void conv_mma(const float* __restrict__ s_g,
              const float* __restrict__ t_g,
              float* __restrict__ out) {
    extern __shared__ char smem[];
    float* stgf = (float*)(smem + OFF_STG);
    const int tid = threadIdx.x, wid = tid >> 5, lane = tid & 31;
    const int gid = lane >> 2, tig = lane & 3;
    const int lq = blockIdx.x, b = blockIdx.y, cg = blockIdx.z;
    const int lbase = lq * 8;
    const float* tbase = t_g + (((size_t)b * 16 + cg * 2) * 64 + lbase + wid) * 63;

    // ---- prologue: stage s tile coalesced into staging region ----
    float* s_raw = stgf;
    {
        const float* sgb = s_g + ((size_t)b * 1024 + lbase) * 63;   // 16B-aligned
        for (int i = tid; i < 2016; i += 256) {                     // 16 m * 126 f4
            int m = i / 126, j = i - m * 126;
            float4 v = *(const float4*)(sgb + (size_t)m * 4032 + j * 4);
            *(float4*)(s_raw + m * SRS + j * 4) = v;
        }
    }
    __syncthreads();

    // ---- warp-local B build: warp w -> l = w; lane = (m, h) ----
    {
        int m = lane >> 1, h = lane & 1;
        const float* sp = s_raw + m * SRS + wid * 63 + h * 32;
        u32 hw[16], lw[16];
        #pragma unroll
        for (int q = 0; q < 16; q++) {
            float x0 = sp[2 * q];                    // k = h*32+2q <= 62
            float x1 = 0.0f;
            if (h * 32 + 2 * q + 1 < 63) x1 = sp[2 * q + 1];
            u32 u0 = __float_as_uint(x0), u1 = __float_as_uint(x1);
            hw[q] = __byte_perm(u0, u1, 0x7632);
            float h0 = __uint_as_float(u0 & 0xFFFF0000u);
            float h1 = __uint_as_float(u1 & 0xFFFF0000u);
            lw[q] = pack_bf2(x0 - h0, x1 - h1);
        }
        char* bh = smem + OFF_B + wid * B_PERL + m * 144 + h * 64;
        char* bl = bh + B_SIDE;
        #pragma unroll
        for (int cc = 0; cc < 4; cc++) {
            *(uint4*)(bh + cc * 16) =
                make_uint4(hw[cc*4], hw[cc*4+1], hw[cc*4+2], hw[cc*4+3]);
            *(uint4*)(bl + cc * 16) =
                make_uint4(lw[cc*4], lw[cc*4+1], lw[cc*4+2], lw[cc*4+3]);
        }
    }
    // ---- warp-local A build for first c ----
    build_A(smem, tbase, wid, lane);
    __syncthreads();   // s_raw consumed -> staging free; B/A(c0) ready

    const int l_off = lane & 7, qq = lane >> 3;
    const int sk = (gid & 4) << 2;                 // A half-swizzle offset
    const char* ab = smem + OFF_A + wid * A_PERL;
    const char* bb = smem + OFF_B + wid * B_PERL;

    #pragma unroll 1
    for (int ci = 0; ci < 2; ci++) {
        const int c = cg * 2 + ci;

        #pragma unroll 1
        for (int p = 0; p < 2; p++) {          // p doubles as nt
            // ---- mainloop half: n-tile nt = p for this warp's l ----
            float acc[8][4];
            u32 bfr[4][2][2];   // [kt][side][b0/b1]
            #pragma unroll
            for (int kt = 0; kt < 4; kt++)
                #pragma unroll
                for (int sd = 0; sd < 2; sd++) {
                    const char* ad = bb + sd * B_SIDE + (8 * p + gid) * 144
                                   + kt * 32 + tig * 4;
                    bfr[kt][sd][0] = *(const u32*)ad;
                    bfr[kt][sd][1] = *(const u32*)(ad + 16);
                }
            #pragma unroll
            for (int md = 0; md < 8; md++)
                #pragma unroll
                for (int e = 0; e < 4; e++) acc[md][e] = 0.0f;

            #pragma unroll
            for (int sg = 0; sg < 5; sg++) {               // sigma = md - kt
                const char* ar = ab + sg * 512 + gid * 32 + tig * 4;
                u32 ah4[4] = { *(const u32*)(ar + sk),
                               *(const u32*)(ar + 256 + sk),
                               *(const u32*)(ar + (16 - sk)),
                               *(const u32*)(ar + 256 + (16 - sk)) };
                const char* alp = ar + A_SIDE;
                u32 al4[4] = { *(const u32*)(alp + sk),
                               *(const u32*)(alp + 256 + sk),
                               *(const u32*)(alp + (16 - sk)),
                               *(const u32*)(alp + 256 + (16 - sk)) };
                #pragma unroll
                for (int kt = 0; kt < 4; kt++) {
                    const int md = sg + kt;                // 0..7
                    mma_bf16(acc[md], ah4, bfr[kt][0][0], bfr[kt][0][1]); // hi*hi
                    mma_bf16(acc[md], ah4, bfr[kt][1][0], bfr[kt][1][1]); // hi*lo
                    mma_bf16(acc[md], al4, bfr[kt][0][0], bfr[kt][0][1]); // lo*hi
                }
            }

            // ---- hoisted A build for c+1 (own slice; overlaps epilogue) ----
            if (p == 1 && ci < 1)
                build_A(smem, tbase + (size_t)(ci + 1) * 64 * 63, wid, lane);

            __syncthreads();   // staging writable (prev store readers done)

            // ---- stage this half's 8 m ----
            #pragma unroll
            for (int md = 0; md < 8; md++) {
                int d0 = 16 * md + gid;
                float* st = stgf + (2 * tig) * STG_MS + d0 * 9 + wid;
                st[0]            = acc[md][0];
                st[STG_MS]       = acc[md][1];
                st[72]           = acc[md][2];
                st[STG_MS + 72]  = acc[md][3];
            }
            __syncthreads();

            // ---- store (streamed) ----
            int m = 8 * p + wid;
            int a = (c - m) & 15;
            float* ob = out + ((size_t)(b * 256 + a * 16 + c) << 13)
                      + (size_t)(8 * qq) * 64 + lbase + l_off;
            const float* sm_m = stgf + wid * STG_MS + 72 * qq + l_off;
            #pragma unroll
            for (int jj = 0; jj < 32; jj++) {
                int dlo = jj & 7, dhi = jj >> 3;
                __stcs(ob + (size_t)(dlo + 32 * dhi) * 64,
                       sm_m[9 * dlo + 288 * dhi]);
            }
            // no trailing barrier: next mma half touches only warp-private
            // A/B; the next pre-stage barrier protects the staging region.
        }
    }
}

extern "C" void kernel_launch(void* const* d_in, const int* in_sizes, int n_in,
                              void* d_out, int out_size) {
    const float* s = (const float*)d_in[0];
    const float* t = (const float*)d_in[1];
    float* out = (float*)d_out;

    cudaFuncSetAttribute(conv_mma,
                         cudaFuncAttributeMaxDynamicSharedMemorySize, SMEM_TOTAL);

    dim3 grid(8, 32, 8);   // (l-oct, b, c-pair) = 2048 blocks, 2 c's each
    conv_mma<<<grid, 256, SMEM_TOTAL>>>(s, t, out);
}